// round 10
// baseline (speedup 1.0000x reference)
#include <cuda_runtime.h>
#include <cstddef>

// LSTM_31018253812286 — f32x2 FFMA2 SIMT, v9: v8 + distance-2 weight prefetch
// (weights stream from L2 at 234-262 cyc; distance-1 coverage ~256 cyc was
// marginal, distance-2 gives ~512 cyc -> fully covered).
//
// B=131072, T=5, I=13, H=256, OUT=6.
// CTA: TB=64 batches, 256 threads (8 warps; warp w owns batch octet w — h and
// c traffic is entirely warp-private, columns b0..b0+7 -> __syncwarp only).
// Thread owns hidden pair (n0,n0+1) per chunk x 8 batches; accumulators are
// f32x2 u64 via PTX fma.rn.f32x2 (SASS FFMA2, 2 FMA/instr).
// Weights half-split [k][half][p][4]: each warp LDG.128 is a dense 512B span.
// c in smem (register pressure ~175, no spills). h/c strides padded to 68.
// Head fused into per-timestep epilogue; W1 prefolded to [t][n][8].

#define H_   256
#define IN_  13
#define T_   5
#define OUT_ 6
#define TB   64
#define HS   68     // padded row stride (floats) for h and c
#define NTHREADS 256
#define NP   (H_ / 2)   // 128 n-pairs

typedef unsigned long long u64;

__device__ __forceinline__ u64 pack2(float x) {
    u64 r; asm("mov.b64 %0, {%1, %1};" : "=l"(r) : "f"(x)); return r;
}
__device__ __forceinline__ void fma2(u64& d, u64 a, u64 b) {
    asm("fma.rn.f32x2 %0, %1, %2, %0;" : "+l"(d) : "l"(a), "l"(b));
}
__device__ __forceinline__ float2 unpack2(u64 v) {
    float2 r; asm("mov.b64 {%0, %1}, %2;" : "=f"(r.x), "=f"(r.y) : "l"(v)); return r;
}

// __device__ scratch (built by prep kernel; no allocations).
// 16B alignment REQUIRED: main kernel uses 128-bit loads.
//  g_Wt2 [k][half][p][4] : half=g>>1, gi=g&1, e=n&1, p=n>>1
//  g_Wih2[i][half][p][4]
//  g_bias2  [half][p][4] : b_ih + b_hh
//  g_W1p [t][n][8]      : W1[o][t*H+n] at slot o (o<6); slots 6,7 unread pad
__device__ __align__(16) float g_Wt2[H_ * 4 * H_];
__device__ __align__(16) float g_Wih2[IN_ * 4 * H_];
__device__ __align__(16) float g_bias2[4 * H_];
__device__ __align__(16) float g_W1p[T_ * H_ * 8];

__global__ void lstm_prep_31018253812286(const float* __restrict__ W_ih,
                                         const float* __restrict__ W_hh,
                                         const float* __restrict__ b_ih,
                                         const float* __restrict__ b_hh,
                                         const float* __restrict__ W1) {
    const int stride = gridDim.x * blockDim.x;
    const int idx0 = blockIdx.x * blockDim.x + threadIdx.x;
    // W_hh row-major [4H][H]: row = g*256 + n, col = k.
    for (int idx = idx0; idx < 4 * H_ * H_; idx += stride) {
        int row  = idx / H_;
        int k    = idx - row * H_;
        int g    = row >> 8;
        int n    = row & (H_ - 1);
        int p    = n >> 1, e = n & 1;
        int half = g >> 1, gi = g & 1;
        g_Wt2[(((k * 2 + half) * NP) + p) * 4 + gi * 2 + e] = W_hh[idx];
    }
    // W_ih row-major [4H][I].
    for (int idx = idx0; idx < 4 * H_ * IN_; idx += stride) {
        int row  = idx / IN_;
        int i    = idx - row * IN_;
        int g    = row >> 8;
        int n    = row & (H_ - 1);
        int p    = n >> 1, e = n & 1;
        int half = g >> 1, gi = g & 1;
        g_Wih2[(((i * 2 + half) * NP) + p) * 4 + gi * 2 + e] = W_ih[idx];
    }
    for (int idx = idx0; idx < 4 * H_; idx += stride) {
        int g    = idx >> 8;
        int n    = idx & (H_ - 1);
        int p    = n >> 1, e = n & 1;
        int half = g >> 1, gi = g & 1;
        g_bias2[(half * NP + p) * 4 + gi * 2 + e] = b_ih[idx] + b_hh[idx];
    }
    // W1 row-major [OUT][T*H] -> [t][n][8] (slots 6,7 never read).
    for (int idx = idx0; idx < OUT_ * T_ * H_; idx += stride) {
        int o = idx / (T_ * H_);
        int r = idx - o * (T_ * H_);   // r = t*H + n
        g_W1p[r * 8 + o] = W1[idx];
    }
}

__device__ __forceinline__ float sigmoid_f(float x) {
    return __fdividef(1.0f, 1.0f + __expf(-x));
}
__device__ __forceinline__ float tanh_f(float x) {
    return __fdividef(2.0f, 1.0f + __expf(-2.0f * x)) - 1.0f;
}

__global__ void __launch_bounds__(NTHREADS, 1)
lstm_main_31018253812286(const float* __restrict__ x,
                         const float* __restrict__ b1,
                         float* __restrict__ out) {
    extern __shared__ float smem[];
    float* h_s = smem;                       // [2][H_][HS] = 139264 B
    float* c_s = smem + 2 * H_ * HS;         // [H_][HS]    =  69632 B
    float* x_s = smem + 3 * H_ * HS;         // [T_][IN_][TB] = 16640 B
                                             // total 225536 B

    const int tid = threadIdx.x;
    const int tn  = tid & 31;   // lane -> n-pair within chunk
    const int wq  = tid >> 5;   // warp id -> batch octet
    const int b0  = wq * 8;

    // Stage this CTA's input sequence (coalesced read, transposed store).
    {
        const float* xg = x + (size_t)blockIdx.x * TB * (T_ * IN_);
        for (int idx = tid; idx < TB * T_ * IN_; idx += NTHREADS) {
            int b = idx / (T_ * IN_);
            int r = idx - b * (T_ * IN_);
            int t = r / IN_;
            int i = r - t * IN_;
            x_s[(t * IN_ + i) * TB + b] = xg[idx];
        }
    }
    __syncthreads();   // only CTA-wide barrier: x_s is read-only afterwards

    float part[OUT_][8];        // fused-head partials
    #pragma unroll
    for (int o = 0; o < OUT_; o++)
        #pragma unroll
        for (int bi = 0; bi < 8; bi++) part[o][bi] = 0.0f;

    for (int t = 0; t < T_; t++) {
        const int wbuf = t & 1;
        const int rbuf = wbuf ^ 1;
        const float* hread  = h_s + rbuf * (H_ * HS);
        float*       hwrite = h_s + wbuf * (H_ * HS);

        #pragma unroll
        for (int ch = 0; ch < 4; ch++) {
            const int p  = ch * 32 + tn;      // n-pair index; n0 = 2*p
            const int n0 = p * 2;
            u64 acc[4][8];                    // [gate][batch], packed (n0, n0+1)

            // Init with combined bias: two dense 16B reads (half0: g0,g1; half1: g2,g3).
            {
                ulonglong2 h0 = *(const ulonglong2*)(g_bias2 + (0 * NP + p) * 4);
                ulonglong2 h1 = *(const ulonglong2*)(g_bias2 + (1 * NP + p) * 4);
                u64 bv[4] = {h0.x, h0.y, h1.x, h1.y};
                #pragma unroll
                for (int g = 0; g < 4; g++)
                    #pragma unroll
                    for (int bi = 0; bi < 8; bi++) acc[g][bi] = bv[g];
            }

            // Input projection (13 k-steps). Dense half-split weight loads.
            #pragma unroll
            for (int i = 0; i < IN_; i++) {
                float4 xa4 = *(const float4*)(x_s + (t * IN_ + i) * TB + b0);
                float4 xb4 = *(const float4*)(x_s + (t * IN_ + i) * TB + b0 + 4);
                u64 xa[8] = {pack2(xa4.x), pack2(xa4.y), pack2(xa4.z), pack2(xa4.w),
                             pack2(xb4.x), pack2(xb4.y), pack2(xb4.z), pack2(xb4.w)};
                const float* wb = g_Wih2 + (i * 2 * NP + p) * 4;
                ulonglong2 w01 = *(const ulonglong2*)(wb);            // half0: g0,g1
                ulonglong2 w23 = *(const ulonglong2*)(wb + NP * 4);   // half1: g2,g3
                u64 wv[4] = {w01.x, w01.y, w23.x, w23.y};
                #pragma unroll
                for (int g = 0; g < 4; g++)
                    #pragma unroll
                    for (int bi = 0; bi < 8; bi++) fma2(acc[g][bi], wv[g], xa[bi]);
            }

            // Recurrent GEMM (skipped at t=0: h0 = 0). FFMA2 mainloop with a
            // 3-deep rotating weight-register pipeline: w(kk+2) is issued to
            // L2 while the FMA block consumes w(kk) (~512 cyc coverage vs
            // 234-262 cyc L2 latency). h reads are warp-uniform broadcasts
            // from this warp's private smem columns.
            if (t > 0) {
                ulonglong2 wA01 = *(const ulonglong2*)(g_Wt2 + p * 4);
                ulonglong2 wA23 = *(const ulonglong2*)(g_Wt2 + p * 4 + NP * 4);
                ulonglong2 wB01 = *(const ulonglong2*)(g_Wt2 + (2 * NP + p) * 4);
                ulonglong2 wB23 = *(const ulonglong2*)(g_Wt2 + (2 * NP + p) * 4 + NP * 4);
                #pragma unroll 4
                for (int kk = 0; kk < H_; kk++) {
                    u64 wv[4] = {wA01.x, wA01.y, wA23.x, wA23.y};   // consume kk
                    wA01 = wB01; wA23 = wB23;                       // rotate
                    if (kk + 2 < H_) {                              // prefetch kk+2
                        const float* wn = g_Wt2 + ((kk + 2) * 2 * NP + p) * 4;
                        wB01 = *(const ulonglong2*)(wn);
                        wB23 = *(const ulonglong2*)(wn + NP * 4);
                    }
                    float4 ha4 = *(const float4*)(hread + kk * HS + b0);      // bcast
                    float4 hb4 = *(const float4*)(hread + kk * HS + b0 + 4);  // bcast
                    u64 ha[8] = {pack2(ha4.x), pack2(ha4.y), pack2(ha4.z), pack2(ha4.w),
                                 pack2(hb4.x), pack2(hb4.y), pack2(hb4.z), pack2(hb4.w)};
                    #pragma unroll
                    for (int g = 0; g < 4; g++)
                        #pragma unroll
                        for (int bi = 0; bi < 8; bi++) fma2(acc[g][bi], wv[g], ha[bi]);
                }
            }

            // Epilogue: unpack, activations, smem cell update, h write, fused head.
            #pragma unroll
            for (int e = 0; e < 2; e++) {
                const int n = n0 + e;
                float* crow = c_s + n * HS + b0;

                // Previous cell state (warp-private smem; zeros at t==0).
                float cold[8];
                if (t > 0) {
                    float4 ca = *(const float4*)(crow);
                    float4 cb = *(const float4*)(crow + 4);
                    cold[0]=ca.x; cold[1]=ca.y; cold[2]=ca.z; cold[3]=ca.w;
                    cold[4]=cb.x; cold[5]=cb.y; cold[6]=cb.z; cold[7]=cb.w;
                } else {
                    #pragma unroll
                    for (int bi = 0; bi < 8; bi++) cold[bi] = 0.0f;
                }

                float hq[8], cnew[8];
                #pragma unroll
                for (int bi = 0; bi < 8; bi++) {
                    float2 ia = unpack2(acc[0][bi]);
                    float2 fa = unpack2(acc[1][bi]);
                    float2 ga = unpack2(acc[2][bi]);
                    float2 oa = unpack2(acc[3][bi]);
                    float gi = e ? ia.y : ia.x;
                    float gf = e ? fa.y : fa.x;
                    float gg = e ? ga.y : ga.x;
                    float go = e ? oa.y : oa.x;
                    float iv = sigmoid_f(gi);
                    float fv = sigmoid_f(gf);
                    float gv = tanh_f(gg);
                    float ov = sigmoid_f(go);
                    float cv = fmaf(fv, cold[bi], iv * gv);
                    cnew[bi] = cv;
                    hq[bi] = ov * tanh_f(cv);
                }

                *(float4*)(crow)     = make_float4(cnew[0], cnew[1], cnew[2], cnew[3]);
                *(float4*)(crow + 4) = make_float4(cnew[4], cnew[5], cnew[6], cnew[7]);

                // Prefolded head weights: one float4 + one float2 (32B row).
                const float* wr = g_W1p + (t * H_ + n) * 8;
                float4 wa = *(const float4*)(wr);
                float2 wb2 = *(const float2*)(wr + 4);
                float w1v[OUT_] = {wa.x, wa.y, wa.z, wa.w, wb2.x, wb2.y};
                #pragma unroll
                for (int bi = 0; bi < 8; bi++)
                    #pragma unroll
                    for (int o = 0; o < OUT_; o++)
                        part[o][bi] = fmaf(hq[bi], w1v[o], part[o][bi]);

                *(float4*)(hwrite + n * HS + b0) =
                    make_float4(hq[0], hq[1], hq[2], hq[3]);
                *(float4*)(hwrite + n * HS + b0 + 4) =
                    make_float4(hq[4], hq[5], hq[6], hq[7]);
            }
        }
        __syncwarp();   // h and c are warp-private: warp-local fence suffices
    }

    // Warp-reduce fused-head partials (32 lanes cover all 256 n).
    #pragma unroll
    for (int o = 0; o < OUT_; o++)
        #pragma unroll
        for (int bi = 0; bi < 8; bi++) {
            float v = part[o][bi];
            #pragma unroll
            for (int m = 16; m >= 1; m >>= 1)
                v += __shfl_xor_sync(0xffffffffu, v, m);
            part[o][bi] = v;
        }
    if (tn == 0) {
        const size_t bg0 = (size_t)blockIdx.x * TB + b0;
        #pragma unroll
        for (int bi = 0; bi < 8; bi++)
            #pragma unroll
            for (int o = 0; o < OUT_; o++)
                out[(bg0 + bi) * OUT_ + o] = part[o][bi] + b1[o];
    }
}

extern "C" void kernel_launch(void* const* d_in, const int* in_sizes, int n_in,
                              void* d_out, int out_size) {
    const float* x    = (const float*)d_in[0];  // [B,5,13]
    const float* W_ih = (const float*)d_in[1];  // [1024,13]
    const float* W_hh = (const float*)d_in[2];  // [1024,256]
    const float* b_ih = (const float*)d_in[3];  // [1024]
    const float* b_hh = (const float*)d_in[4];  // [1024]
    const float* W1   = (const float*)d_in[5];  // [6,1280]
    const float* b1   = (const float*)d_in[6];  // [6]
    float* out = (float*)d_out;                 // [B,6]

    const int B = in_sizes[0] / (T_ * IN_);     // 131072
    const int smem_bytes = (3 * H_ * HS + T_ * IN_ * TB) * (int)sizeof(float); // 225536

    cudaFuncSetAttribute(lstm_main_31018253812286,
                         cudaFuncAttributeMaxDynamicSharedMemorySize, smem_bytes);

    lstm_prep_31018253812286<<<64, 256>>>(W_ih, W_hh, b_ih, b_hh, W1);
    lstm_main_31018253812286<<<B / TB, NTHREADS, smem_bytes>>>(x, b1, out);
}

// round 14
// speedup vs baseline: 1.1074x; 1.1074x over previous
#include <cuda_runtime.h>
#include <cstddef>

// LSTM_31018253812286 — f32x2 FFMA2 SIMT, v10c (resubmit; never executed).
// Post-mortem of v9 (8408us, regs=255 SPILLED, occ=12.5%, fma=44%):
// halve per-thread state (4 batches/thread), double warps (512 thr, 16 warps).
// Mainloop register demand ~110 < 128 cap -> no mainloop spills; 4 warps/SMSP
// for latency hiding. v9's L2=4% confirmed L1tex MSHR merging dedups the
// cross-warp weight replication, so 16 warps cost L1tex wavefronts only.
// Branch-free epilogue: c_s zero-filled once at staging (t==0 case removed).
//
// B=131072, T=5, I=13, H=256, OUT=6.
// CTA: TB=64 batches, 512 threads; warp w owns batch quad b0=4w (h/c warp-
// private -> __syncwarp only). Thread owns hidden pair (n0,n0+1) per chunk x
// 4 batches; accumulators f32x2 u64 via fma.rn.f32x2 (FFMA2).
// Weights half-split [k][half][p][4], L2-streamed, distance-2 prefetch.
// c in smem; h/c strides padded to 68; W1 prefolded [t][n][8]; head fused.

#define H_   256
#define IN_  13
#define T_   5
#define OUT_ 6
#define TB   64
#define HS   68     // padded row stride (floats) for h and c
#define NTHREADS 512
#define NP   (H_ / 2)   // 128 n-pairs

typedef unsigned long long u64;

__device__ __forceinline__ u64 pack2(float x) {
    u64 r; asm("mov.b64 %0, {%1, %1};" : "=l"(r) : "f"(x)); return r;
}
__device__ __forceinline__ void fma2(u64& d, u64 a, u64 b) {
    asm("fma.rn.f32x2 %0, %1, %2, %0;" : "+l"(d) : "l"(a), "l"(b));
}
__device__ __forceinline__ float2 unpack2(u64 v) {
    float2 r; asm("mov.b64 {%0, %1}, %2;" : "=f"(r.x), "=f"(r.y) : "l"(v)); return r;
}

// __device__ scratch (built by prep kernel; no allocations). 16B-aligned for
// 128-bit loads.
//  g_Wt2 [k][half][p][4] : half=g>>1, gi=g&1, e=n&1, p=n>>1
//  g_Wih2[i][half][p][4]
//  g_bias2  [half][p][4] : b_ih + b_hh
//  g_W1p [t][n][8]      : W1[o][t*H+n] at slot o (o<6); slots 6,7 unread pad
__device__ __align__(16) float g_Wt2[H_ * 4 * H_];
__device__ __align__(16) float g_Wih2[IN_ * 4 * H_];
__device__ __align__(16) float g_bias2[4 * H_];
__device__ __align__(16) float g_W1p[T_ * H_ * 8];

__global__ void lstm_prep_31018253812286(const float* __restrict__ W_ih,
                                         const float* __restrict__ W_hh,
                                         const float* __restrict__ b_ih,
                                         const float* __restrict__ b_hh,
                                         const float* __restrict__ W1) {
    const int stride = gridDim.x * blockDim.x;
    const int idx0 = blockIdx.x * blockDim.x + threadIdx.x;
    for (int idx = idx0; idx < 4 * H_ * H_; idx += stride) {
        int row  = idx / H_;
        int k    = idx - row * H_;
        int g    = row >> 8;
        int n    = row & (H_ - 1);
        int p    = n >> 1, e = n & 1;
        int half = g >> 1, gi = g & 1;
        g_Wt2[(((k * 2 + half) * NP) + p) * 4 + gi * 2 + e] = W_hh[idx];
    }
    for (int idx = idx0; idx < 4 * H_ * IN_; idx += stride) {
        int row  = idx / IN_;
        int i    = idx - row * IN_;
        int g    = row >> 8;
        int n    = row & (H_ - 1);
        int p    = n >> 1, e = n & 1;
        int half = g >> 1, gi = g & 1;
        g_Wih2[(((i * 2 + half) * NP) + p) * 4 + gi * 2 + e] = W_ih[idx];
    }
    for (int idx = idx0; idx < 4 * H_; idx += stride) {
        int g    = idx >> 8;
        int n    = idx & (H_ - 1);
        int p    = n >> 1, e = n & 1;
        int half = g >> 1, gi = g & 1;
        g_bias2[(half * NP + p) * 4 + gi * 2 + e] = b_ih[idx] + b_hh[idx];
    }
    for (int idx = idx0; idx < OUT_ * T_ * H_; idx += stride) {
        int o = idx / (T_ * H_);
        int r = idx - o * (T_ * H_);   // r = t*H + n
        g_W1p[r * 8 + o] = W1[idx];
    }
}

__device__ __forceinline__ float sigmoid_f(float x) {
    return __fdividef(1.0f, 1.0f + __expf(-x));
}
__device__ __forceinline__ float tanh_f(float x) {
    return __fdividef(2.0f, 1.0f + __expf(-2.0f * x)) - 1.0f;
}

__global__ void __launch_bounds__(NTHREADS, 1)
lstm_main_31018253812286(const float* __restrict__ x,
                         const float* __restrict__ b1,
                         float* __restrict__ out) {
    extern __shared__ float smem[];
    float* h_s = smem;                       // [2][H_][HS] = 139264 B
    float* c_s = smem + 2 * H_ * HS;         // [H_][HS]    =  69632 B
    float* x_s = smem + 3 * H_ * HS;         // [T_][IN_][TB] = 16640 B
                                             // total 225536 B

    const int tid = threadIdx.x;
    const int tn  = tid & 31;   // lane -> n-pair within chunk
    const int wq  = tid >> 5;   // warp id -> batch quad
    const int b0  = wq * 4;

    // Stage input sequence (coalesced read, transposed store) + zero c_s
    // (branch-free epilogue reads c_s even at t==0).
    {
        const float* xg = x + (size_t)blockIdx.x * TB * (T_ * IN_);
        for (int idx = tid; idx < TB * T_ * IN_; idx += NTHREADS) {
            int b = idx / (T_ * IN_);
            int r = idx - b * (T_ * IN_);
            int t = r / IN_;
            int i = r - t * IN_;
            x_s[(t * IN_ + i) * TB + b] = xg[idx];
        }
        for (int idx = tid; idx < H_ * HS; idx += NTHREADS)
            c_s[idx] = 0.0f;
    }
    __syncthreads();   // only CTA-wide barrier: x_s read-only, c_s zeroed

    float part[OUT_][4];        // fused-head partials (cold across mainloop)
    #pragma unroll
    for (int o = 0; o < OUT_; o++)
        #pragma unroll
        for (int bi = 0; bi < 4; bi++) part[o][bi] = 0.0f;

    for (int t = 0; t < T_; t++) {
        const int wbuf = t & 1;
        const int rbuf = wbuf ^ 1;
        const float* hread  = h_s + rbuf * (H_ * HS);
        float*       hwrite = h_s + wbuf * (H_ * HS);

        #pragma unroll
        for (int ch = 0; ch < 4; ch++) {
            const int p  = ch * 32 + tn;      // n-pair index; n0 = 2*p
            const int n0 = p * 2;
            u64 acc[4][4];                    // [gate][batch], packed (n0, n0+1)

            // Init with combined bias (half0: g0,g1; half1: g2,g3).
            {
                ulonglong2 h0 = *(const ulonglong2*)(g_bias2 + (0 * NP + p) * 4);
                ulonglong2 h1 = *(const ulonglong2*)(g_bias2 + (1 * NP + p) * 4);
                u64 bv[4] = {h0.x, h0.y, h1.x, h1.y};
                #pragma unroll
                for (int g = 0; g < 4; g++)
                    #pragma unroll
                    for (int bi = 0; bi < 4; bi++) acc[g][bi] = bv[g];
            }

            // Input projection (13 k-steps).
            #pragma unroll
            for (int i = 0; i < IN_; i++) {
                float4 xa4 = *(const float4*)(x_s + (t * IN_ + i) * TB + b0);
                u64 xa[4] = {pack2(xa4.x), pack2(xa4.y), pack2(xa4.z), pack2(xa4.w)};
                const float* wb = g_Wih2 + (i * 2 * NP + p) * 4;
                ulonglong2 w01 = *(const ulonglong2*)(wb);
                ulonglong2 w23 = *(const ulonglong2*)(wb + NP * 4);
                u64 wv[4] = {w01.x, w01.y, w23.x, w23.y};
                #pragma unroll
                for (int g = 0; g < 4; g++)
                    #pragma unroll
                    for (int bi = 0; bi < 4; bi++) fma2(acc[g][bi], wv[g], xa[bi]);
            }

            // Recurrent GEMM (skipped at t=0). 3-deep rotating weight-register
            // pipeline (distance-2 -> ~512 cyc coverage vs 234-262 cyc L2).
            if (t > 0) {
                ulonglong2 wA01 = *(const ulonglong2*)(g_Wt2 + p * 4);
                ulonglong2 wA23 = *(const ulonglong2*)(g_Wt2 + p * 4 + NP * 4);
                ulonglong2 wB01 = *(const ulonglong2*)(g_Wt2 + (2 * NP + p) * 4);
                ulonglong2 wB23 = *(const ulonglong2*)(g_Wt2 + (2 * NP + p) * 4 + NP * 4);
                #pragma unroll 4
                for (int kk = 0; kk < H_; kk++) {
                    u64 wv[4] = {wA01.x, wA01.y, wA23.x, wA23.y};   // consume kk
                    wA01 = wB01; wA23 = wB23;                       // rotate
                    if (kk + 2 < H_) {                              // prefetch kk+2
                        const float* wn = g_Wt2 + ((kk + 2) * 2 * NP + p) * 4;
                        wB01 = *(const ulonglong2*)(wn);
                        wB23 = *(const ulonglong2*)(wn + NP * 4);
                    }
                    float4 ha4 = *(const float4*)(hread + kk * HS + b0);  // bcast
                    u64 ha[4] = {pack2(ha4.x), pack2(ha4.y), pack2(ha4.z), pack2(ha4.w)};
                    #pragma unroll
                    for (int g = 0; g < 4; g++)
                        #pragma unroll
                        for (int bi = 0; bi < 4; bi++) fma2(acc[g][bi], wv[g], ha[bi]);
                }
            }

            // Epilogue (branch-free): activations, smem cell update, h write,
            // fused head. c_s pre-zeroed so t==0 needs no special case.
            #pragma unroll
            for (int e = 0; e < 2; e++) {
                const int n = n0 + e;
                float* crow = c_s + n * HS + b0;

                float4 ca = *(const float4*)(crow);
                float cold[4] = {ca.x, ca.y, ca.z, ca.w};

                float hq[4], cnew[4];
                #pragma unroll
                for (int bi = 0; bi < 4; bi++) {
                    float2 ia = unpack2(acc[0][bi]);
                    float2 fa = unpack2(acc[1][bi]);
                    float2 ga = unpack2(acc[2][bi]);
                    float2 oa = unpack2(acc[3][bi]);
                    float gi = e ? ia.y : ia.x;
                    float gf = e ? fa.y : fa.x;
                    float gg = e ? ga.y : ga.x;
                    float go = e ? oa.y : oa.x;
                    float iv = sigmoid_f(gi);
                    float fv = sigmoid_f(gf);
                    float gv = tanh_f(gg);
                    float ov = sigmoid_f(go);
                    float cv = fmaf(fv, cold[bi], iv * gv);
                    cnew[bi] = cv;
                    hq[bi] = ov * tanh_f(cv);
                }

                *(float4*)(crow) = make_float4(cnew[0], cnew[1], cnew[2], cnew[3]);
                *(float4*)(hwrite + n * HS + b0) =
                    make_float4(hq[0], hq[1], hq[2], hq[3]);

                // Prefolded head weights: one float4 + one float2 (32B row).
                const float* wr = g_W1p + (t * H_ + n) * 8;
                float4 wa = *(const float4*)(wr);
                float2 wb2 = *(const float2*)(wr + 4);
                float w1v[OUT_] = {wa.x, wa.y, wa.z, wa.w, wb2.x, wb2.y};
                #pragma unroll
                for (int bi = 0; bi < 4; bi++)
                    #pragma unroll
                    for (int o = 0; o < OUT_; o++)
                        part[o][bi] = fmaf(hq[bi], w1v[o], part[o][bi]);
            }
        }
        __syncwarp();   // h and c are warp-private: warp-local fence suffices
    }

    // Warp-reduce fused-head partials (32 lanes cover all 256 n).
    #pragma unroll
    for (int o = 0; o < OUT_; o++)
        #pragma unroll
        for (int bi = 0; bi < 4; bi++) {
            float v = part[o][bi];
            #pragma unroll
            for (int m = 16; m >= 1; m >>= 1)
                v += __shfl_xor_sync(0xffffffffu, v, m);
            part[o][bi] = v;
        }
    if (tn == 0) {
        const size_t bg0 = (size_t)blockIdx.x * TB + b0;
        #pragma unroll
        for (int bi = 0; bi < 4; bi++)
            #pragma unroll
            for (int o = 0; o < OUT_; o++)
                out[(bg0 + bi) * OUT_ + o] = part[o][bi] + b1[o];
    }
}

extern "C" void kernel_launch(void* const* d_in, const int* in_sizes, int n_in,
                              void* d_out, int out_size) {
    const float* x    = (const float*)d_in[0];  // [B,5,13]
    const float* W_ih = (const float*)d_in[1];  // [1024,13]
    const float* W_hh = (const float*)d_in[2];  // [1024,256]
    const float* b_ih = (const float*)d_in[3];  // [1024]
    const float* b_hh = (const float*)d_in[4];  // [1024]
    const float* W1   = (const float*)d_in[5];  // [6,1280]
    const float* b1   = (const float*)d_in[6];  // [6]
    float* out = (float*)d_out;                 // [B,6]

    const int B = in_sizes[0] / (T_ * IN_);     // 131072
    const int smem_bytes = (3 * H_ * HS + T_ * IN_ * TB) * (int)sizeof(float); // 225536

    cudaFuncSetAttribute(lstm_main_31018253812286,
                         cudaFuncAttributeMaxDynamicSharedMemorySize, smem_bytes);

    lstm_prep_31018253812286<<<64, 256>>>(W_ih, W_hh, b_ih, b_hh, W1);
    lstm_main_31018253812286<<<B / TB, NTHREADS, smem_bytes>>>(x, b1, out);
}

// round 16
// speedup vs baseline: 1.2379x; 1.1179x over previous
#include <cuda_runtime.h>
#include <cstddef>

// LSTM_31018253812286 — v11b: batch-packed f32x2 (lane = scalar n, 8 batches
// per thread packed as 4 f32x2 pairs) + NAMED-BARRIER fix (v11 had a race:
// n-halves split across warp pairs means h is pair-shared, not warp-private;
// bar.sync oct+1,64 orders the (oct,0)/(oct,1) pair each timestep).
//
// Why: v10c measured 7593us with fma pinned at 49.8% = L1tex-wavefront
// co-bound (128 weight wf per 128-cyc FMA window). This layout halves weight
// bytes/MAC: one float4 per k covers all 4 gates -> 96 wf / 128 cyc.
//
// B=131072, T=5, I=13, H=256, OUT=6.
// CTA: TB=64, 512 threads, 16 warps = 8 batch-octets x 2 n-halves.
// Warp (oct,nh): batches b0=8*oct..+8; n = nh*128 + ch*32 + lane, 4 chunks.
// Weights [k][n][4g] (dense 512B/warp LDG.128), distance-2 prefetch.
// h/c in smem, stride 68. W1 prefolded [t][n][8]; head packed FFMA2;
// cross-nh reduce via x_s scratch.

#define H_   256
#define IN_  13
#define T_   5
#define OUT_ 6
#define TB   64
#define HS   68
#define NTHREADS 512

typedef unsigned long long u64;

__device__ __forceinline__ u64 pack2(float x) {
    u64 r; asm("mov.b64 %0, {%1, %1};" : "=l"(r) : "f"(x)); return r;
}
__device__ __forceinline__ u64 packxy(float x, float y) {
    u64 r; asm("mov.b64 %0, {%1, %2};" : "=l"(r) : "f"(x), "f"(y)); return r;
}
__device__ __forceinline__ void fma2(u64& d, u64 a, u64 b) {
    asm("fma.rn.f32x2 %0, %1, %2, %0;" : "+l"(d) : "l"(a), "l"(b));
}
__device__ __forceinline__ float2 unpack2(u64 v) {
    float2 r; asm("mov.b64 {%0, %1}, %2;" : "=f"(r.x), "=f"(r.y) : "l"(v)); return r;
}

// __device__ scratch (prep kernel; no allocations). 16B-aligned.
//  g_W3 [k][n][4g], g_Wi3[i][n][4g], g_b3[n][4g], g_W1p[t][n][8]
__device__ __align__(16) float g_W3[H_ * H_ * 4];
__device__ __align__(16) float g_Wi3[IN_ * H_ * 4];
__device__ __align__(16) float g_b3[H_ * 4];
__device__ __align__(16) float g_W1p[T_ * H_ * 8];

__global__ void lstm_prep_31018253812286(const float* __restrict__ W_ih,
                                         const float* __restrict__ W_hh,
                                         const float* __restrict__ b_ih,
                                         const float* __restrict__ b_hh,
                                         const float* __restrict__ W1) {
    const int stride = gridDim.x * blockDim.x;
    const int idx0 = blockIdx.x * blockDim.x + threadIdx.x;
    // W_hh row-major [4H][H]: row = g*256+n, col = k -> [k][n][g]
    for (int idx = idx0; idx < 4 * H_ * H_; idx += stride) {
        int row = idx / H_;
        int k   = idx - row * H_;
        int g   = row >> 8;
        int n   = row & (H_ - 1);
        g_W3[(k * H_ + n) * 4 + g] = W_hh[idx];
    }
    // W_ih row-major [4H][I] -> [i][n][g]
    for (int idx = idx0; idx < 4 * H_ * IN_; idx += stride) {
        int row = idx / IN_;
        int i   = idx - row * IN_;
        int g   = row >> 8;
        int n   = row & (H_ - 1);
        g_Wi3[(i * H_ + n) * 4 + g] = W_ih[idx];
    }
    for (int idx = idx0; idx < 4 * H_; idx += stride) {
        int g = idx >> 8;
        int n = idx & (H_ - 1);
        g_b3[n * 4 + g] = b_ih[idx] + b_hh[idx];
    }
    // W1 [OUT][T*H] -> [t][n][8] (slots 6,7 pad, never read)
    for (int idx = idx0; idx < OUT_ * T_ * H_; idx += stride) {
        int o = idx / (T_ * H_);
        int r = idx - o * (T_ * H_);
        g_W1p[r * 8 + o] = W1[idx];
    }
}

__device__ __forceinline__ float sigmoid_f(float x) {
    return __fdividef(1.0f, 1.0f + __expf(-x));
}
__device__ __forceinline__ float tanh_f(float x) {
    return __fdividef(2.0f, 1.0f + __expf(-2.0f * x)) - 1.0f;
}

__global__ void __launch_bounds__(NTHREADS, 1)
lstm_main_31018253812286(const float* __restrict__ x,
                         const float* __restrict__ b1,
                         float* __restrict__ out) {
    extern __shared__ float smem[];
    float* h_s = smem;                       // [2][H_][HS] = 139264 B
    float* c_s = smem + 2 * H_ * HS;         // [H_][HS]    =  69632 B
    float* x_s = smem + 3 * H_ * HS;         // [T_][IN_][TB] = 16640 B (also
                                             // reused as reduce scratch at end)

    const int tid = threadIdx.x;
    const int tn  = tid & 31;        // lane -> n within chunk
    const int w   = tid >> 5;        // warp id
    const int oct = w & 7;           // batch octet
    const int nh  = w >> 3;          // n-half (0: n<128, 1: n>=128)
    const int b0  = oct * 8;

    // Stage x (coalesced read, transposed store) + zero c_s.
    {
        const float* xg = x + (size_t)blockIdx.x * TB * (T_ * IN_);
        for (int idx = tid; idx < TB * T_ * IN_; idx += NTHREADS) {
            int b = idx / (T_ * IN_);
            int r = idx - b * (T_ * IN_);
            int t = r / IN_;
            int i = r - t * IN_;
            x_s[(t * IN_ + i) * TB + b] = xg[idx];
        }
        for (int idx = tid; idx < H_ * HS; idx += NTHREADS)
            c_s[idx] = 0.0f;
    }
    __syncthreads();

    u64 part[OUT_][4];               // fused-head partials, batch-pair packed
    #pragma unroll
    for (int o = 0; o < OUT_; o++)
        #pragma unroll
        for (int bp = 0; bp < 4; bp++) part[o][bp] = 0ull;

    for (int t = 0; t < T_; t++) {
        const int wbuf = t & 1;
        const float* hread  = h_s + (wbuf ^ 1) * (H_ * HS);
        float*       hwrite = h_s + wbuf * (H_ * HS);

        #pragma unroll
        for (int ch = 0; ch < 4; ch++) {
            const int n = nh * 128 + ch * 32 + tn;
            u64 acc[4][4];           // [gate][batch-pair]

            // Bias: one float4, splat per gate (n-uniform across batch lanes).
            {
                float4 bv = *(const float4*)(g_b3 + n * 4);
                u64 bs[4] = {pack2(bv.x), pack2(bv.y), pack2(bv.z), pack2(bv.w)};
                #pragma unroll
                for (int g = 0; g < 4; g++)
                    #pragma unroll
                    for (int bp = 0; bp < 4; bp++) acc[g][bp] = bs[g];
            }

            // Input projection (13 k-steps): 1 LDG.128 weights + x batch-pairs.
            #pragma unroll
            for (int i = 0; i < IN_; i++) {
                float4 wv4 = *(const float4*)(g_Wi3 + (i * H_ + n) * 4);
                u64 ws[4] = {pack2(wv4.x), pack2(wv4.y), pack2(wv4.z), pack2(wv4.w)};
                const float* xrow = x_s + (t * IN_ + i) * TB + b0;
                ulonglong2 xp0 = *(const ulonglong2*)(xrow);
                ulonglong2 xp1 = *(const ulonglong2*)(xrow + 4);
                u64 xp[4] = {xp0.x, xp0.y, xp1.x, xp1.y};
                #pragma unroll
                for (int g = 0; g < 4; g++)
                    #pragma unroll
                    for (int bp = 0; bp < 4; bp++) fma2(acc[g][bp], ws[g], xp[bp]);
            }

            // Recurrent GEMM (skipped at t=0). Distance-2 float4 weight
            // prefetch (~512 cyc coverage vs 234-262 cyc L2).
            if (t > 0) {
                float4 wA = *(const float4*)(g_W3 + (0 * H_ + n) * 4);
                float4 wB = *(const float4*)(g_W3 + (1 * H_ + n) * 4);
                #pragma unroll 4
                for (int kk = 0; kk < H_; kk++) {
                    float4 wv4 = wA; wA = wB;
                    if (kk + 2 < H_)
                        wB = *(const float4*)(g_W3 + ((kk + 2) * H_ + n) * 4);
                    u64 ws[4] = {pack2(wv4.x), pack2(wv4.y), pack2(wv4.z), pack2(wv4.w)};
                    const float* hrow = hread + kk * HS + b0;   // uniform bcast
                    ulonglong2 hp0 = *(const ulonglong2*)(hrow);
                    ulonglong2 hp1 = *(const ulonglong2*)(hrow + 4);
                    u64 hp[4] = {hp0.x, hp0.y, hp1.x, hp1.y};
                    #pragma unroll
                    for (int g = 0; g < 4; g++)
                        #pragma unroll
                        for (int bp = 0; bp < 4; bp++) fma2(acc[g][bp], ws[g], hp[bp]);
                }
            }

            // Epilogue: activations (8 batches, 1 n), c/h smem update, head.
            {
                float* crow = c_s + n * HS + b0;
                float4 c0 = *(const float4*)(crow);
                float4 c1 = *(const float4*)(crow + 4);
                float cold[8] = {c0.x, c0.y, c0.z, c0.w, c1.x, c1.y, c1.z, c1.w};

                float hq[8], cnew[8];
                #pragma unroll
                for (int bp = 0; bp < 4; bp++) {
                    float2 iv2 = unpack2(acc[0][bp]);
                    float2 fv2 = unpack2(acc[1][bp]);
                    float2 gv2 = unpack2(acc[2][bp]);
                    float2 ov2 = unpack2(acc[3][bp]);
                    #pragma unroll
                    for (int hf = 0; hf < 2; hf++) {
                        int b = bp * 2 + hf;
                        float iv = sigmoid_f(hf ? iv2.y : iv2.x);
                        float fv = sigmoid_f(hf ? fv2.y : fv2.x);
                        float gv = tanh_f(hf ? gv2.y : gv2.x);
                        float ov = sigmoid_f(hf ? ov2.y : ov2.x);
                        float cv = fmaf(fv, cold[b], iv * gv);
                        cnew[b] = cv;
                        hq[b] = ov * tanh_f(cv);
                    }
                }

                *(float4*)(crow)     = make_float4(cnew[0], cnew[1], cnew[2], cnew[3]);
                *(float4*)(crow + 4) = make_float4(cnew[4], cnew[5], cnew[6], cnew[7]);
                float* hrow = hwrite + n * HS + b0;
                *(float4*)(hrow)     = make_float4(hq[0], hq[1], hq[2], hq[3]);
                *(float4*)(hrow + 4) = make_float4(hq[4], hq[5], hq[6], hq[7]);

                // Fused head: packed FFMA2 into part.
                const float* wr = g_W1p + (t * H_ + n) * 8;
                float4 wa = *(const float4*)(wr);
                float2 wb2 = *(const float2*)(wr + 4);
                float w1v[OUT_] = {wa.x, wa.y, wa.z, wa.w, wb2.x, wb2.y};
                u64 hqp[4] = {packxy(hq[0], hq[1]), packxy(hq[2], hq[3]),
                              packxy(hq[4], hq[5]), packxy(hq[6], hq[7])};
                #pragma unroll
                for (int o = 0; o < OUT_; o++) {
                    u64 ws1 = pack2(w1v[o]);
                    #pragma unroll
                    for (int bp = 0; bp < 4; bp++) fma2(part[o][bp], ws1, hqp[bp]);
                }
            }
        }
        // h is shared between the two nh-warps of this octet (each reads all
        // 256 rows next timestep) -> named barrier over the 64-thread pair.
        // ids 1..8 (id 0 belongs to __syncthreads).
        asm volatile("bar.sync %0, 64;" :: "r"(oct + 1) : "memory");
    }

    // Reduce part over the warp's 32 lanes (n within this nh half).
    #pragma unroll
    for (int o = 0; o < OUT_; o++)
        #pragma unroll
        for (int bp = 0; bp < 4; bp++) {
            float2 v = unpack2(part[o][bp]);
            #pragma unroll
            for (int m = 16; m >= 1; m >>= 1) {
                v.x += __shfl_xor_sync(0xffffffffu, v.x, m);
                v.y += __shfl_xor_sync(0xffffffffu, v.y, m);
            }
            part[o][bp] = packxy(v.x, v.y);
        }

    // Cross-nh reduction via x_s scratch (x_s no longer needed).
    __syncthreads();
    float* scratch = x_s;    // [16 warps][48 floats]
    if (tn == 0) {
        #pragma unroll
        for (int o = 0; o < OUT_; o++)
            #pragma unroll
            for (int bp = 0; bp < 4; bp++) {
                float2 v = unpack2(part[o][bp]);
                scratch[w * 48 + o * 8 + bp * 2 + 0] = v.x;
                scratch[w * 48 + o * 8 + bp * 2 + 1] = v.y;
            }
    }
    __syncthreads();
    if (nh == 0) {
        const size_t bg0 = (size_t)blockIdx.x * TB + b0;
        #pragma unroll
        for (int rep = 0; rep < 2; rep++) {
            int idx = tn + rep * 32;
            if (idx < 48) {
                int o  = idx / 8;
                int bs = idx - o * 8;
                float v = scratch[w * 48 + idx] + scratch[(w + 8) * 48 + idx] + b1[o];
                out[(bg0 + bs) * OUT_ + o] = v;
            }
        }
    }
}

extern "C" void kernel_launch(void* const* d_in, const int* in_sizes, int n_in,
                              void* d_out, int out_size) {
    const float* x    = (const float*)d_in[0];  // [B,5,13]
    const float* W_ih = (const float*)d_in[1];  // [1024,13]
    const float* W_hh = (const float*)d_in[2];  // [1024,256]
    const float* b_ih = (const float*)d_in[3];  // [1024]
    const float* b_hh = (const float*)d_in[4];  // [1024]
    const float* W1   = (const float*)d_in[5];  // [6,1280]
    const float* b1   = (const float*)d_in[6];  // [6]
    float* out = (float*)d_out;                 // [B,6]

    const int B = in_sizes[0] / (T_ * IN_);     // 131072
    const int smem_bytes = (3 * H_ * HS + T_ * IN_ * TB) * (int)sizeof(float); // 225536

    cudaFuncSetAttribute(lstm_main_31018253812286,
                         cudaFuncAttributeMaxDynamicSharedMemorySize, smem_bytes);

    lstm_prep_31018253812286<<<64, 256>>>(W_ih, W_hh, b_ih, b_hh, W1);
    lstm_main_31018253812286<<<B / TB, NTHREADS, smem_bytes>>>(x, b1, out);
}